// round 6
// baseline (speedup 1.0000x reference)
#include <cuda_runtime.h>
#include <math.h>

#define Bz 256
#define Sz 256
#define Mz 50
#define MP 25          // slot pairs
#define WST 52         // g_w row stride (padded, 16B-aligned float4 rows)
#define DQz 64
#define DVz 128
#define Fz 128
#define NQ1 10001
#define NQA1 20001
#define NROWS (Bz*Sz)

typedef unsigned long long u64;

// ---- packed f32x2 helpers (sm_103a FFMA2 path, PTX-only) -------------------
__device__ __forceinline__ u64 pack2(float lo, float hi) {
    u64 r; asm("mov.b64 %0, {%1, %2};" : "=l"(r) : "f"(lo), "f"(hi)); return r;
}
__device__ __forceinline__ void unpack2(u64 v, float& lo, float& hi) {
    asm("mov.b64 {%0, %1}, %2;" : "=f"(lo), "=f"(hi) : "l"(v));
}
__device__ __forceinline__ u64 fma2(u64 a, u64 b, u64 c) {
    u64 d; asm("fma.rn.f32x2 %0, %1, %2, %3;" : "=l"(d) : "l"(a), "l"(b), "l"(c)); return d;
}
__device__ __forceinline__ u64 add2(u64 a, u64 b) {
    u64 d; asm("add.rn.f32x2 %0, %1, %2;" : "=l"(d) : "l"(a), "l"(b)); return d;
}

// Scratch (static device globals — no allocation allowed)
__device__ float g_w[NQ1 * WST];
__device__ float g_er[NQA1 * DVz];
__device__ float g_ad[NQA1 * DVz];
__device__ float g_qr[NQ1 * Fz];
__device__ float g_reads[NROWS * DVz];
__device__ float g_acc[2];

// ---------------------------------------------------------------------------
__global__ void k_init() {
    if (threadIdx.x < 2) g_acc[threadIdx.x] = 0.0f;
}

// ---------------------------------------------------------------------------
__global__ void k_w(const float* __restrict__ q_table,
                    const float* __restrict__ key_mem) {
    __shared__ float key_s[Mz * DQz];
    int tid = threadIdx.x;
    for (int i = tid; i < Mz * DQz; i += blockDim.x) key_s[i] = key_mem[i];
    __syncthreads();

    int row = blockIdx.x * 128 + tid;
    if (row >= NQ1) return;

    float q[DQz];
    const float4* qp = (const float4*)(q_table + row * DQz);
#pragma unroll
    for (int i = 0; i < DQz / 4; i++) {
        float4 v = qp[i];
        q[4*i+0] = v.x; q[4*i+1] = v.y; q[4*i+2] = v.z; q[4*i+3] = v.w;
    }

    float sc[Mz];
    float mx = -1e30f;
#pragma unroll
    for (int m = 0; m < Mz; m++) {
        float s = 0.0f;
#pragma unroll
        for (int k = 0; k < DQz; k++) s = fmaf(q[k], key_s[m * DQz + k], s);
        sc[m] = s;
        mx = fmaxf(mx, s);
    }
    float sum = 0.0f;
#pragma unroll
    for (int m = 0; m < Mz; m++) {
        float e = __expf(sc[m] - mx);
        sc[m] = e;
        sum += e;
    }
    float inv = 1.0f / sum;
#pragma unroll
    for (int m = 0; m < Mz; m++) g_w[row * WST + m] = sc[m] * inv;
    g_w[row * WST + 50] = 0.0f;
    g_w[row * WST + 51] = 0.0f;
}

// ---------------------------------------------------------------------------
// q-part of the head: g_qr[i,:] = q_table[i,:] @ W_read[128:192,:]
#define QR_ROWS 64
#define QR_SMEM_FLOATS (64*128 + QR_ROWS*DQz)
__global__ void __launch_bounds__(512) k_qr(const float* __restrict__ q_table,
                                            const float* __restrict__ W_read) {
    extern __shared__ float sm[];
    float* W2 = sm;
    float* xs = W2 + 64 * 128;

    int tid = threadIdx.x;
    for (int i = tid; i < 64 * 128 / 4; i += 512)
        ((float4*)W2)[i] = ((const float4*)(W_read + 128 * 128))[i];

    int row0 = blockIdx.x * QR_ROWS;
    for (int idx = tid; idx < QR_ROWS * 16; idx += 512) {
        int r = idx >> 4, c = idx & 15;
        int row = row0 + r;
        float4 v = make_float4(0.f, 0.f, 0.f, 0.f);
        if (row < NQ1) v = ((const float4*)(q_table + (long)row * DQz))[c];
        ((float4*)xs)[r * 16 + c] = v;
    }
    __syncthreads();

    int rg = tid >> 4;
    int fg = tid & 15;
    u64 acc[2][4];
#pragma unroll
    for (int r = 0; r < 2; r++)
#pragma unroll
        for (int j = 0; j < 4; j++) acc[r][j] = 0ull;

#pragma unroll 4
    for (int k = 0; k < 64; k++) {
        const ulonglong2* wv = (const ulonglong2*)(W2 + k * 128 + fg * 8);
        ulonglong2 w01 = wv[0], w23 = wv[1];
#pragma unroll
        for (int r = 0; r < 2; r++) {
            float xv = xs[(rg * 2 + r) * DQz + k];
            u64 xp = pack2(xv, xv);
            acc[r][0] = fma2(xp, w01.x, acc[r][0]);
            acc[r][1] = fma2(xp, w01.y, acc[r][1]);
            acc[r][2] = fma2(xp, w23.x, acc[r][2]);
            acc[r][3] = fma2(xp, w23.y, acc[r][3]);
        }
    }

#pragma unroll
    for (int r = 0; r < 2; r++) {
        int row = row0 + rg * 2 + r;
        if (row < NQ1) {
            float v[8];
#pragma unroll
            for (int j = 0; j < 4; j++) unpack2(acc[r][j], v[2*j], v[2*j+1]);
            float4* op = (float4*)(g_qr + (long)row * Fz + fg * 8);
            op[0] = make_float4(v[0], v[1], v[2], v[3]);
            op[1] = make_float4(v[4], v[5], v[6], v[7]);
        }
    }
}

// ---------------------------------------------------------------------------
// One activation table (erase OR add): out = act(x @ W + b).
// 64 rows/block, 512 threads, ~97KB smem -> 2 blocks/SM.
#define EA_ROWS 64
#define EA1_SMEM_FLOATS (16384 + EA_ROWS*DVz + 128)
__global__ void __launch_bounds__(512, 2) k_ea1(const float* __restrict__ qa_table,
                     const float* __restrict__ W, const float* __restrict__ bias,
                     int act) {
    extern __shared__ float sm[];
    float* Ws = sm;                 // 128x128
    float* xs = Ws + 16384;         // 64x128
    float* bs = xs + EA_ROWS * DVz; // 128

    int tid = threadIdx.x;
    for (int i = tid; i < 4096; i += 512)
        ((float4*)Ws)[i] = ((const float4*)W)[i];
    if (tid < 128) bs[tid] = bias[tid];

    int row0 = blockIdx.x * EA_ROWS;
    for (int idx = tid; idx < EA_ROWS * 32; idx += 512) {
        int r = idx >> 5, c = idx & 31;
        int row = row0 + r;
        float4 v = make_float4(0.f, 0.f, 0.f, 0.f);
        if (row < NQA1) v = ((const float4*)(qa_table + (long)row * DVz))[c];
        ((float4*)xs)[r * 32 + c] = v;
    }
    __syncthreads();

    int rg = tid >> 4;   // 32 groups of 2 rows
    int fg = tid & 15;   // 8 output cols (4 packed pairs)
    u64 acc[2][4];
#pragma unroll
    for (int r = 0; r < 2; r++)
#pragma unroll
        for (int j = 0; j < 4; j++) acc[r][j] = 0ull;

#pragma unroll 4
    for (int k = 0; k < DVz; k++) {
        const ulonglong2* wv = (const ulonglong2*)(Ws + k * DVz + fg * 8);
        ulonglong2 w01 = wv[0], w23 = wv[1];
#pragma unroll
        for (int r = 0; r < 2; r++) {
            float xv = xs[(rg * 2 + r) * DVz + k];
            u64 xp = pack2(xv, xv);
            acc[r][0] = fma2(xp, w01.x, acc[r][0]);
            acc[r][1] = fma2(xp, w01.y, acc[r][1]);
            acc[r][2] = fma2(xp, w23.x, acc[r][2]);
            acc[r][3] = fma2(xp, w23.y, acc[r][3]);
        }
    }

    float* outp = act ? g_ad : g_er;
#pragma unroll
    for (int r = 0; r < 2; r++) {
        int row = row0 + rg * 2 + r;
        if (row < NQA1) {
            float o8[8];
#pragma unroll
            for (int j = 0; j < 4; j++) {
                int f = fg * 8 + 2 * j;
                float s0, s1;
                unpack2(acc[r][j], s0, s1);
                if (act) {
                    o8[2*j+0] = tanhf(s0 + bs[f]);
                    o8[2*j+1] = tanhf(s1 + bs[f+1]);
                } else {
                    o8[2*j+0] = 1.0f / (1.0f + __expf(-(s0 + bs[f])));
                    o8[2*j+1] = 1.0f / (1.0f + __expf(-(s1 + bs[f+1])));
                }
            }
            float4* op = (float4*)(outp + (long)row * DVz + fg * 8);
            op[0] = make_float4(o8[0], o8[1], o8[2], o8[3]);
            op[1] = make_float4(o8[4], o8[5], o8[6], o8[7]);
        }
    }
}

// ---------------------------------------------------------------------------
// Scan: 128 blocks x 256 threads (2 batches/block, warp-private w staging,
// no block barrier in hot loop). w staged/read as float4/LDS.128.
__global__ void __launch_bounds__(256) k_scan(const int* __restrict__ q_data,
                                              const int* __restrict__ qa_data,
                                              const float* __restrict__ init_value) {
    __shared__ __align__(16) float w_s[8][2][56];   // per-warp double-buffered
    __shared__ int qi_s[2][Sz], qa_s[2][Sz];

    int tid  = threadIdx.x;
    int half = tid >> 7;
    int d    = tid & 127;
    int warp = tid >> 5;
    int lane = tid & 31;

    int b = blockIdx.x * 2 + half;
    int base = b * Sz;

    for (int i = d; i < Sz; i += 128) {
        qi_s[half][i] = q_data[base + i];
        qa_s[half][i] = qa_data[base + i];
    }

    u64 mem[MP];
#pragma unroll
    for (int p = 0; p < MP; p++)
        mem[p] = pack2(init_value[(2*p) * DVz + d], init_value[(2*p+1) * DVz + d]);
    __syncthreads();

    // prime step 0 per warp (13 lanes x float4 covers 50 w + 2 pad)
    if (lane < 13) {
        const float4* wp = (const float4*)(g_w + qi_s[half][0] * WST);
        ((float4*)w_s[warp][0])[lane] = wp[lane];
    }
    float en = g_er[qa_s[half][0] * DVz + d];
    float an = g_ad[qa_s[half][0] * DVz + d];
    __syncwarp();

    int buf = 0;
    for (int s = 0; s < Sz; s++) {
        float e = en, a = an;
        bool flag = (qi_s[half][s] >= 1);

        // prefetch next step (per-warp, decoupled)
        if (s + 1 < Sz) {
            int qan = qa_s[half][s + 1];
            en = g_er[qan * DVz + d];
            an = g_ad[qan * DVz + d];
            if (lane < 13) {
                const float4* wp = (const float4*)(g_w + qi_s[half][s + 1] * WST);
                ((float4*)w_s[warp][buf ^ 1])[lane] = wp[lane];
            }
        }

        u64 ne = pack2(e, e) ^ 0x8000000080000000ull;   // (-e, -e)
        u64 av = pack2(a, a);

        // read: 12 LDS.128 (pairs 0..23) + 1 LDS.64 (pair 24)
        const ulonglong2* wv = (const ulonglong2*)w_s[warp][buf];
        u64 wr[MP];
        u64 r0 = 0ull, r1 = 0ull, r2 = 0ull, r3 = 0ull;
#pragma unroll
        for (int i = 0; i < 12; i += 2) {
            ulonglong2 t0 = wv[i], t1 = wv[i + 1];
            wr[2*i+0] = t0.x; r0 = fma2(t0.x, mem[2*i+0], r0);
            wr[2*i+1] = t0.y; r1 = fma2(t0.y, mem[2*i+1], r1);
            wr[2*i+2] = t1.x; r2 = fma2(t1.x, mem[2*i+2], r2);
            wr[2*i+3] = t1.y; r3 = fma2(t1.y, mem[2*i+3], r3);
        }
        wr[24] = ((const u64*)w_s[warp][buf])[24];
        r0 = fma2(wr[24], mem[24], r0);
        u64 rr = add2(add2(r0, r1), add2(r2, r3));
        float lo, hi;
        unpack2(rr, lo, hi);
        g_reads[(long)(base + s) * DVz + d] = lo + hi;

        // update (uniform branch per warp)
        if (flag) {
#pragma unroll
            for (int p = 0; p < MP; p++) {
                u64 t = fma2(ne, mem[p], av);
                mem[p] = fma2(wr[p], t, mem[p]);
            }
        }

        __syncwarp();
        buf ^= 1;
    }
}

// ---------------------------------------------------------------------------
// Head: K=128 GEMM on reads; 64 rows/block, ~97KB smem -> 2 blocks/SM.
#define HD_ROWS 64
#define HEAD_SMEM_FLOATS (128*128 + HD_ROWS*128 + 128 + 128 + HD_ROWS + 2)
__global__ void __launch_bounds__(512, 2) k_head(const int* __restrict__ q_data,
                       const float* __restrict__ target,
                       const float* __restrict__ W_read, const float* __restrict__ b_read,
                       const float* __restrict__ W_pred, const float* __restrict__ b_pred,
                       float* __restrict__ out) {
    extern __shared__ float sm[];
    float* Ws = sm;                   // 128 x 128
    float* xs = Ws + 128 * 128;       // 64 rows x 128
    float* br = xs + HD_ROWS * 128;
    float* wp = br + 128;
    float* lo = wp + 128;
    float* ls = lo + HD_ROWS;

    int tid = threadIdx.x;
    for (int i = tid; i < 128 * 128 / 4; i += 512)
        ((float4*)Ws)[i] = ((const float4*)W_read)[i];
    if (tid < 128) { br[tid] = b_read[tid]; wp[tid] = W_pred[tid]; }
    if (tid < 2)   ls[tid] = 0.0f;

    int row0 = blockIdx.x * HD_ROWS;
    for (int idx = tid; idx < HD_ROWS * 32; idx += 512) {
        int r = idx >> 5, c = idx & 31;
        int row = row0 + r;
        ((float4*)(xs + r * 128))[c] = ((const float4*)(g_reads + (long)row * DVz))[c];
    }
    __syncthreads();

    int rg = tid >> 4;  // 32 groups x 2 rows
    int fg = tid & 15;  // 8 f-cols (4 packed pairs)
    u64 acc[2][4];
#pragma unroll
    for (int r = 0; r < 2; r++)
#pragma unroll
        for (int j = 0; j < 4; j++) acc[r][j] = 0ull;

#pragma unroll 4
    for (int k = 0; k < 128; k++) {
        const ulonglong2* wv = (const ulonglong2*)(Ws + k * 128 + fg * 8);
        ulonglong2 w01 = wv[0], w23 = wv[1];
#pragma unroll
        for (int r = 0; r < 2; r++) {
            float xv = xs[(rg * 2 + r) * 128 + k];
            u64 xp = pack2(xv, xv);
            acc[r][0] = fma2(xp, w01.x, acc[r][0]);
            acc[r][1] = fma2(xp, w01.y, acc[r][1]);
            acc[r][2] = fma2(xp, w23.x, acc[r][2]);
            acc[r][3] = fma2(xp, w23.y, acc[r][3]);
        }
    }

    float bp = __ldg(b_pred);
#pragma unroll
    for (int r = 0; r < 2; r++) {
        int row = row0 + rg * 2 + r;
        int qi = q_data[row];
        const float4* qrp = (const float4*)(g_qr + (long)qi * Fz + fg * 8);
        float4 q0 = qrp[0], q1 = qrp[1];
        float qv[8] = {q0.x, q0.y, q0.z, q0.w, q1.x, q1.y, q1.z, q1.w};
        float p = 0.0f;
#pragma unroll
        for (int j = 0; j < 4; j++) {
            int f = fg * 8 + 2 * j;
            float s0, s1;
            unpack2(acc[r][j], s0, s1);
            p = fmaf(tanhf(s0 + qv[2*j]   + br[f]),     wp[f],     p);
            p = fmaf(tanhf(s1 + qv[2*j+1] + br[f + 1]), wp[f + 1], p);
        }
#pragma unroll
        for (int off = 8; off >= 1; off >>= 1)
            p += __shfl_down_sync(0xffffffffu, p, off, 16);
        if (fg == 0) lo[rg * 2 + r] = p + bp;
    }
    __syncthreads();

    if (tid < HD_ROWS) {
        int row = row0 + tid;
        float l = lo[tid];
        float prob = 1.0f / (1.0f + __expf(-l));
        out[1 + row] = prob;
        float tt = target[row];
        float bce = 0.0f, cnt = 0.0f;
        if (tt >= 0.0f) {
            bce = fmaxf(l, 0.0f) - l * tt + log1pf(__expf(-fabsf(l)));
            cnt = 1.0f;
        }
#pragma unroll
        for (int off = 16; off >= 1; off >>= 1) {
            bce += __shfl_down_sync(0xffffffffu, bce, off);
            cnt += __shfl_down_sync(0xffffffffu, cnt, off);
        }
        if ((tid & 31) == 0) {
            atomicAdd(&ls[0], bce);
            atomicAdd(&ls[1], cnt);
        }
    }
    __syncthreads();
    if (tid == 0) {
        atomicAdd(&g_acc[0], ls[0]);
        atomicAdd(&g_acc[1], ls[1]);
    }
}

// ---------------------------------------------------------------------------
__global__ void k_fin(float* __restrict__ out) {
    out[0] = g_acc[0] / fmaxf(g_acc[1], 1.0f);
}

// ---------------------------------------------------------------------------
extern "C" void kernel_launch(void* const* d_in, const int* in_sizes, int n_in,
                              void* d_out, int out_size) {
    const int*   q_data    = (const int*)d_in[0];
    const int*   qa_data   = (const int*)d_in[1];
    const float* target    = (const float*)d_in[2];
    const float* q_table   = (const float*)d_in[3];
    const float* qa_table  = (const float*)d_in[4];
    const float* key_mem   = (const float*)d_in[5];
    const float* init_value= (const float*)d_in[6];
    const float* W_e    = (const float*)d_in[7];
    const float* b_e    = (const float*)d_in[8];
    const float* W_a    = (const float*)d_in[9];
    const float* b_a    = (const float*)d_in[10];
    const float* W_read = (const float*)d_in[11];
    const float* b_read = (const float*)d_in[12];
    const float* W_pred = (const float*)d_in[13];
    const float* b_pred = (const float*)d_in[14];
    float* out = (float*)d_out;

    cudaFuncSetAttribute(k_ea1, cudaFuncAttributeMaxDynamicSharedMemorySize,
                         EA1_SMEM_FLOATS * (int)sizeof(float));
    cudaFuncSetAttribute(k_head, cudaFuncAttributeMaxDynamicSharedMemorySize,
                         HEAD_SMEM_FLOATS * (int)sizeof(float));
    cudaFuncSetAttribute(k_qr, cudaFuncAttributeMaxDynamicSharedMemorySize,
                         QR_SMEM_FLOATS * (int)sizeof(float));

    int ea_grid = (NQA1 + EA_ROWS - 1) / EA_ROWS;

    k_init<<<1, 32>>>();
    k_w<<<(NQ1 + 127) / 128, 128>>>(q_table, key_mem);
    k_qr<<<(NQ1 + QR_ROWS - 1) / QR_ROWS, 512, QR_SMEM_FLOATS * sizeof(float)>>>(
        q_table, W_read);
    k_ea1<<<ea_grid, 512, EA1_SMEM_FLOATS * sizeof(float)>>>(qa_table, W_e, b_e, 0);
    k_ea1<<<ea_grid, 512, EA1_SMEM_FLOATS * sizeof(float)>>>(qa_table, W_a, b_a, 1);
    k_scan<<<Bz / 2, 256>>>(q_data, qa_data, init_value);
    k_head<<<NROWS / HD_ROWS, 512, HEAD_SMEM_FLOATS * sizeof(float)>>>(
        q_data, target, W_read, b_read, W_pred, b_pred, out);
    k_fin<<<1, 1>>>(out);
}

// round 7
// speedup vs baseline: 1.2086x; 1.2086x over previous
#include <cuda_runtime.h>
#include <math.h>

#define Bz 256
#define Sz 256
#define Mz 50
#define MP 25          // slot pairs
#define WST 52         // g_w row stride (padded, 16B-aligned float4 rows)
#define DQz 64
#define DVz 128
#define Fz 128
#define NQ1 10001
#define NQA1 20001
#define NROWS (Bz*Sz)

typedef unsigned long long u64;

// ---- packed f32x2 helpers (sm_103a FFMA2 path, PTX-only) -------------------
__device__ __forceinline__ u64 pack2(float lo, float hi) {
    u64 r; asm("mov.b64 %0, {%1, %2};" : "=l"(r) : "f"(lo), "f"(hi)); return r;
}
__device__ __forceinline__ void unpack2(u64 v, float& lo, float& hi) {
    asm("mov.b64 {%0, %1}, %2;" : "=f"(lo), "=f"(hi) : "l"(v));
}
__device__ __forceinline__ u64 fma2(u64 a, u64 b, u64 c) {
    u64 d; asm("fma.rn.f32x2 %0, %1, %2, %3;" : "=l"(d) : "l"(a), "l"(b), "l"(c)); return d;
}
__device__ __forceinline__ u64 add2(u64 a, u64 b) {
    u64 d; asm("add.rn.f32x2 %0, %1, %2;" : "=l"(d) : "l"(a), "l"(b)); return d;
}

// Scratch (static device globals — no allocation allowed)
__device__ float g_w[NQ1 * WST];
__device__ float g_er[NQA1 * DVz];
__device__ float g_ad[NQA1 * DVz];
__device__ float g_qr[NQ1 * Fz];
__device__ float g_reads[NROWS * DVz];
__device__ float g_acc[2];

// ---------------------------------------------------------------------------
__global__ void k_init() {
    if (threadIdx.x < 2) g_acc[threadIdx.x] = 0.0f;
}

// ---------------------------------------------------------------------------
__global__ void k_w(const float* __restrict__ q_table,
                    const float* __restrict__ key_mem) {
    __shared__ float key_s[Mz * DQz];
    int tid = threadIdx.x;
    for (int i = tid; i < Mz * DQz; i += blockDim.x) key_s[i] = key_mem[i];
    __syncthreads();

    int row = blockIdx.x * 128 + tid;
    if (row >= NQ1) return;

    float q[DQz];
    const float4* qp = (const float4*)(q_table + row * DQz);
#pragma unroll
    for (int i = 0; i < DQz / 4; i++) {
        float4 v = qp[i];
        q[4*i+0] = v.x; q[4*i+1] = v.y; q[4*i+2] = v.z; q[4*i+3] = v.w;
    }

    float sc[Mz];
    float mx = -1e30f;
#pragma unroll
    for (int m = 0; m < Mz; m++) {
        float s = 0.0f;
#pragma unroll
        for (int k = 0; k < DQz; k++) s = fmaf(q[k], key_s[m * DQz + k], s);
        sc[m] = s;
        mx = fmaxf(mx, s);
    }
    float sum = 0.0f;
#pragma unroll
    for (int m = 0; m < Mz; m++) {
        float e = __expf(sc[m] - mx);
        sc[m] = e;
        sum += e;
    }
    float inv = 1.0f / sum;
#pragma unroll
    for (int m = 0; m < Mz; m++) g_w[row * WST + m] = sc[m] * inv;
    g_w[row * WST + 50] = 0.0f;
    g_w[row * WST + 51] = 0.0f;
}

// ---------------------------------------------------------------------------
// q-part of the head: g_qr[i,:] = q_table[i,:] @ W_read[128:192,:]
#define QR_ROWS 64
#define QR_SMEM_FLOATS (64*128 + QR_ROWS*DQz)
__global__ void __launch_bounds__(512) k_qr(const float* __restrict__ q_table,
                                            const float* __restrict__ W_read) {
    extern __shared__ float sm[];
    float* W2 = sm;
    float* xs = W2 + 64 * 128;

    int tid = threadIdx.x;
    for (int i = tid; i < 64 * 128 / 4; i += 512)
        ((float4*)W2)[i] = ((const float4*)(W_read + 128 * 128))[i];

    int row0 = blockIdx.x * QR_ROWS;
    for (int idx = tid; idx < QR_ROWS * 16; idx += 512) {
        int r = idx >> 4, c = idx & 15;
        int row = row0 + r;
        float4 v = make_float4(0.f, 0.f, 0.f, 0.f);
        if (row < NQ1) v = ((const float4*)(q_table + (long)row * DQz))[c];
        ((float4*)xs)[r * 16 + c] = v;
    }
    __syncthreads();

    int rg = tid >> 4;
    int fg = tid & 15;
    u64 acc[2][4];
#pragma unroll
    for (int r = 0; r < 2; r++)
#pragma unroll
        for (int j = 0; j < 4; j++) acc[r][j] = 0ull;

#pragma unroll 4
    for (int k = 0; k < 64; k++) {
        const ulonglong2* wv = (const ulonglong2*)(W2 + k * 128 + fg * 8);
        ulonglong2 w01 = wv[0], w23 = wv[1];
#pragma unroll
        for (int r = 0; r < 2; r++) {
            float xv = xs[(rg * 2 + r) * DQz + k];
            u64 xp = pack2(xv, xv);
            acc[r][0] = fma2(xp, w01.x, acc[r][0]);
            acc[r][1] = fma2(xp, w01.y, acc[r][1]);
            acc[r][2] = fma2(xp, w23.x, acc[r][2]);
            acc[r][3] = fma2(xp, w23.y, acc[r][3]);
        }
    }

#pragma unroll
    for (int r = 0; r < 2; r++) {
        int row = row0 + rg * 2 + r;
        if (row < NQ1) {
            float v[8];
#pragma unroll
            for (int j = 0; j < 4; j++) unpack2(acc[r][j], v[2*j], v[2*j+1]);
            float4* op = (float4*)(g_qr + (long)row * Fz + fg * 8);
            op[0] = make_float4(v[0], v[1], v[2], v[3]);
            op[1] = make_float4(v[4], v[5], v[6], v[7]);
        }
    }
}

// ---------------------------------------------------------------------------
// Fused erase/add tables. Grid = 2*157 blocks; block picks one table.
// 256 threads, 128 rows/block, 8x8 register tile per thread -> fma-bound.
#define EA_ROWS 128
#define EA_HALF ((NQA1 + EA_ROWS - 1) / EA_ROWS)   // 157
#define EA_SMEM_FLOATS (16384 + EA_ROWS*DVz + 128)
__global__ void __launch_bounds__(256) k_ea(const float* __restrict__ qa_table,
                     const float* __restrict__ W_e, const float* __restrict__ b_e,
                     const float* __restrict__ W_a, const float* __restrict__ b_a) {
    extern __shared__ float sm[];
    float* Ws = sm;                 // 128x128
    float* xs = Ws + 16384;         // 128x128
    float* bs = xs + EA_ROWS * DVz; // 128

    int bid = blockIdx.x;
    int act = (bid >= EA_HALF) ? 1 : 0;
    int rowblk = act ? bid - EA_HALF : bid;
    const float* W    = act ? W_a : W_e;
    const float* bias = act ? b_a : b_e;

    int tid = threadIdx.x;
    for (int i = tid; i < 4096; i += 256)
        ((float4*)Ws)[i] = ((const float4*)W)[i];
    if (tid < 128) bs[tid] = bias[tid];

    int row0 = rowblk * EA_ROWS;
    for (int idx = tid; idx < EA_ROWS * 32; idx += 256) {
        int r = idx >> 5, c = idx & 31;
        int row = row0 + r;
        float4 v = make_float4(0.f, 0.f, 0.f, 0.f);
        if (row < NQA1) v = ((const float4*)(qa_table + (long)row * DVz))[c];
        ((float4*)xs)[r * 32 + c] = v;
    }
    __syncthreads();

    int rg = tid >> 4;   // 16 groups x 8 rows
    int fg = tid & 15;   // 8 output cols (4 packed pairs)
    u64 acc[8][4];
#pragma unroll
    for (int r = 0; r < 8; r++)
#pragma unroll
        for (int j = 0; j < 4; j++) acc[r][j] = 0ull;

#pragma unroll 2
    for (int k = 0; k < DVz; k++) {
        const ulonglong2* wv = (const ulonglong2*)(Ws + k * DVz + fg * 8);
        ulonglong2 w01 = wv[0], w23 = wv[1];
#pragma unroll
        for (int r = 0; r < 8; r++) {
            float xv = xs[(rg * 8 + r) * DVz + k];
            u64 xp = pack2(xv, xv);
            acc[r][0] = fma2(xp, w01.x, acc[r][0]);
            acc[r][1] = fma2(xp, w01.y, acc[r][1]);
            acc[r][2] = fma2(xp, w23.x, acc[r][2]);
            acc[r][3] = fma2(xp, w23.y, acc[r][3]);
        }
    }

    float* outp = act ? g_ad : g_er;
#pragma unroll
    for (int r = 0; r < 8; r++) {
        int row = row0 + rg * 8 + r;
        if (row < NQA1) {
            float o8[8];
#pragma unroll
            for (int j = 0; j < 4; j++) {
                int f = fg * 8 + 2 * j;
                float s0, s1;
                unpack2(acc[r][j], s0, s1);
                if (act) {
                    o8[2*j+0] = tanhf(s0 + bs[f]);
                    o8[2*j+1] = tanhf(s1 + bs[f+1]);
                } else {
                    o8[2*j+0] = 1.0f / (1.0f + __expf(-(s0 + bs[f])));
                    o8[2*j+1] = 1.0f / (1.0f + __expf(-(s1 + bs[f+1])));
                }
            }
            float4* op = (float4*)(outp + (long)row * DVz + fg * 8);
            op[0] = make_float4(o8[0], o8[1], o8[2], o8[3]);
            op[1] = make_float4(o8[4], o8[5], o8[6], o8[7]);
        }
    }
}

// ---------------------------------------------------------------------------
// Scan: 128 blocks x 256 threads (2 batches/block), warp-private w staging,
// no block barrier in hot loop, TWO-step-deep prefetch of w/e/a.
__global__ void __launch_bounds__(256) k_scan(const int* __restrict__ q_data,
                                              const int* __restrict__ qa_data,
                                              const float* __restrict__ init_value) {
    __shared__ __align__(16) float w_s[8][3][56];   // per-warp triple-buffered
    __shared__ int qi_s[2][Sz], qa_s[2][Sz];

    int tid  = threadIdx.x;
    int half = tid >> 7;
    int d    = tid & 127;
    int warp = tid >> 5;
    int lane = tid & 31;

    int b = blockIdx.x * 2 + half;
    int base = b * Sz;

    for (int i = d; i < Sz; i += 128) {
        qi_s[half][i] = q_data[base + i];
        qa_s[half][i] = qa_data[base + i];
    }

    u64 mem[MP];
#pragma unroll
    for (int p = 0; p < MP; p++)
        mem[p] = pack2(init_value[(2*p) * DVz + d], init_value[(2*p+1) * DVz + d]);
    __syncthreads();

    // prime steps 0 and 1
    if (lane < 13) {
        ((float4*)w_s[warp][0])[lane] =
            ((const float4*)(g_w + qi_s[half][0] * WST))[lane];
        ((float4*)w_s[warp][1])[lane] =
            ((const float4*)(g_w + qi_s[half][1] * WST))[lane];
    }
    float e0 = g_er[qa_s[half][0] * DVz + d];
    float a0 = g_ad[qa_s[half][0] * DVz + d];
    float e1 = g_er[qa_s[half][1] * DVz + d];
    float a1 = g_ad[qa_s[half][1] * DVz + d];
    __syncwarp();

    int buf = 0;
    for (int s = 0; s < Sz; s++) {
        bool flag = (qi_s[half][s] >= 1);

        // issue prefetch for step s+2 (two-deep: covers ~2 step times of lat)
        float e2 = 0.0f, a2 = 0.0f;
        if (s + 2 < Sz) {
            int qan = qa_s[half][s + 2];
            e2 = g_er[qan * DVz + d];
            a2 = g_ad[qan * DVz + d];
            if (lane < 13) {
                int nb = buf + 2; if (nb >= 3) nb -= 3;
                ((float4*)w_s[warp][nb])[lane] =
                    ((const float4*)(g_w + qi_s[half][s + 2] * WST))[lane];
            }
        }

        u64 ne = pack2(e0, e0) ^ 0x8000000080000000ull;   // (-e, -e)
        u64 av = pack2(a0, a0);

        // read: 12 LDS.128 (pairs 0..23) + 1 LDS.64 (pair 24)
        const ulonglong2* wv = (const ulonglong2*)w_s[warp][buf];
        u64 wr[MP];
        u64 r0 = 0ull, r1 = 0ull, r2 = 0ull, r3 = 0ull;
#pragma unroll
        for (int i = 0; i < 12; i += 2) {
            ulonglong2 t0 = wv[i], t1 = wv[i + 1];
            wr[2*i+0] = t0.x; r0 = fma2(t0.x, mem[2*i+0], r0);
            wr[2*i+1] = t0.y; r1 = fma2(t0.y, mem[2*i+1], r1);
            wr[2*i+2] = t1.x; r2 = fma2(t1.x, mem[2*i+2], r2);
            wr[2*i+3] = t1.y; r3 = fma2(t1.y, mem[2*i+3], r3);
        }
        wr[24] = ((const u64*)w_s[warp][buf])[24];
        r0 = fma2(wr[24], mem[24], r0);
        u64 rr = add2(add2(r0, r1), add2(r2, r3));
        float lo, hi;
        unpack2(rr, lo, hi);
        g_reads[(long)(base + s) * DVz + d] = lo + hi;

        // update (uniform branch per warp)
        if (flag) {
#pragma unroll
            for (int p = 0; p < MP; p++) {
                u64 t = fma2(ne, mem[p], av);
                mem[p] = fma2(wr[p], t, mem[p]);
            }
        }

        // rotate prefetch registers / buffers
        e0 = e1; a0 = a1;
        e1 = e2; a1 = a2;
        __syncwarp();
        buf += 1; if (buf == 3) buf = 0;
    }
}

// ---------------------------------------------------------------------------
// Head: K=128 GEMM on reads; 256 threads, 128 rows/block, 8x8 register tile.
#define HD_ROWS 128
#define HEAD_SMEM_FLOATS (128*128 + HD_ROWS*128 + 128 + 128 + HD_ROWS + 2)
__global__ void __launch_bounds__(256) k_head(const int* __restrict__ q_data,
                       const float* __restrict__ target,
                       const float* __restrict__ W_read, const float* __restrict__ b_read,
                       const float* __restrict__ W_pred, const float* __restrict__ b_pred,
                       float* __restrict__ out) {
    extern __shared__ float sm[];
    float* Ws = sm;                   // 128 x 128
    float* xs = Ws + 128 * 128;       // 128 rows x 128
    float* br = xs + HD_ROWS * 128;
    float* wp = br + 128;
    float* lo = wp + 128;
    float* ls = lo + HD_ROWS;

    int tid = threadIdx.x;
    for (int i = tid; i < 128 * 128 / 4; i += 256)
        ((float4*)Ws)[i] = ((const float4*)W_read)[i];
    if (tid < 128) { br[tid] = b_read[tid]; wp[tid] = W_pred[tid]; }
    if (tid < 2)   ls[tid] = 0.0f;

    int row0 = blockIdx.x * HD_ROWS;
    for (int idx = tid; idx < HD_ROWS * 32; idx += 256) {
        int r = idx >> 5, c = idx & 31;
        int row = row0 + r;
        ((float4*)(xs + r * 128))[c] = ((const float4*)(g_reads + (long)row * DVz))[c];
    }
    __syncthreads();

    int rg = tid >> 4;  // 16 groups x 8 rows
    int fg = tid & 15;  // 8 f-cols (4 packed pairs)
    u64 acc[8][4];
#pragma unroll
    for (int r = 0; r < 8; r++)
#pragma unroll
        for (int j = 0; j < 4; j++) acc[r][j] = 0ull;

#pragma unroll 2
    for (int k = 0; k < 128; k++) {
        const ulonglong2* wv = (const ulonglong2*)(Ws + k * 128 + fg * 8);
        ulonglong2 w01 = wv[0], w23 = wv[1];
#pragma unroll
        for (int r = 0; r < 8; r++) {
            float xv = xs[(rg * 8 + r) * 128 + k];
            u64 xp = pack2(xv, xv);
            acc[r][0] = fma2(xp, w01.x, acc[r][0]);
            acc[r][1] = fma2(xp, w01.y, acc[r][1]);
            acc[r][2] = fma2(xp, w23.x, acc[r][2]);
            acc[r][3] = fma2(xp, w23.y, acc[r][3]);
        }
    }

    float bp = __ldg(b_pred);
#pragma unroll
    for (int r = 0; r < 8; r++) {
        int row = row0 + rg * 8 + r;
        int qi = q_data[row];
        const float4* qrp = (const float4*)(g_qr + (long)qi * Fz + fg * 8);
        float4 q0 = qrp[0], q1 = qrp[1];
        float qv[8] = {q0.x, q0.y, q0.z, q0.w, q1.x, q1.y, q1.z, q1.w};
        float p = 0.0f;
#pragma unroll
        for (int j = 0; j < 4; j++) {
            int f = fg * 8 + 2 * j;
            float s0, s1;
            unpack2(acc[r][j], s0, s1);
            p = fmaf(tanhf(s0 + qv[2*j]   + br[f]),     wp[f],     p);
            p = fmaf(tanhf(s1 + qv[2*j+1] + br[f + 1]), wp[f + 1], p);
        }
#pragma unroll
        for (int off = 8; off >= 1; off >>= 1)
            p += __shfl_down_sync(0xffffffffu, p, off, 16);
        if (fg == 0) lo[rg * 8 + r] = p + bp;
    }
    __syncthreads();

    if (tid < HD_ROWS) {
        int row = row0 + tid;
        float l = lo[tid];
        float prob = 1.0f / (1.0f + __expf(-l));
        out[1 + row] = prob;
        float tt = target[row];
        float bce = 0.0f, cnt = 0.0f;
        if (tt >= 0.0f) {
            bce = fmaxf(l, 0.0f) - l * tt + log1pf(__expf(-fabsf(l)));
            cnt = 1.0f;
        }
#pragma unroll
        for (int off = 16; off >= 1; off >>= 1) {
            bce += __shfl_down_sync(0xffffffffu, bce, off);
            cnt += __shfl_down_sync(0xffffffffu, cnt, off);
        }
        if ((tid & 31) == 0) {
            atomicAdd(&ls[0], bce);
            atomicAdd(&ls[1], cnt);
        }
    }
    __syncthreads();
    if (tid == 0) {
        atomicAdd(&g_acc[0], ls[0]);
        atomicAdd(&g_acc[1], ls[1]);
    }
}

// ---------------------------------------------------------------------------
__global__ void k_fin(float* __restrict__ out) {
    out[0] = g_acc[0] / fmaxf(g_acc[1], 1.0f);
}

// ---------------------------------------------------------------------------
extern "C" void kernel_launch(void* const* d_in, const int* in_sizes, int n_in,
                              void* d_out, int out_size) {
    const int*   q_data    = (const int*)d_in[0];
    const int*   qa_data   = (const int*)d_in[1];
    const float* target    = (const float*)d_in[2];
    const float* q_table   = (const float*)d_in[3];
    const float* qa_table  = (const float*)d_in[4];
    const float* key_mem   = (const float*)d_in[5];
    const float* init_value= (const float*)d_in[6];
    const float* W_e    = (const float*)d_in[7];
    const float* b_e    = (const float*)d_in[8];
    const float* W_a    = (const float*)d_in[9];
    const float* b_a    = (const float*)d_in[10];
    const float* W_read = (const float*)d_in[11];
    const float* b_read = (const float*)d_in[12];
    const float* W_pred = (const float*)d_in[13];
    const float* b_pred = (const float*)d_in[14];
    float* out = (float*)d_out;

    cudaFuncSetAttribute(k_ea, cudaFuncAttributeMaxDynamicSharedMemorySize,
                         EA_SMEM_FLOATS * (int)sizeof(float));
    cudaFuncSetAttribute(k_head, cudaFuncAttributeMaxDynamicSharedMemorySize,
                         HEAD_SMEM_FLOATS * (int)sizeof(float));
    cudaFuncSetAttribute(k_qr, cudaFuncAttributeMaxDynamicSharedMemorySize,
                         QR_SMEM_FLOATS * (int)sizeof(float));

    k_init<<<1, 32>>>();
    k_w<<<(NQ1 + 127) / 128, 128>>>(q_table, key_mem);
    k_qr<<<(NQ1 + QR_ROWS - 1) / QR_ROWS, 512, QR_SMEM_FLOATS * sizeof(float)>>>(
        q_table, W_read);
    k_ea<<<2 * EA_HALF, 256, EA_SMEM_FLOATS * sizeof(float)>>>(
        qa_table, W_e, b_e, W_a, b_a);
    k_scan<<<Bz / 2, 256>>>(q_data, qa_data, init_value);
    k_head<<<NROWS / HD_ROWS, 256, HEAD_SMEM_FLOATS * sizeof(float)>>>(
        q_data, target, W_read, b_read, W_pred, b_pred, out);
    k_fin<<<1, 1>>>(out);
}

// round 8
// speedup vs baseline: 1.4416x; 1.1927x over previous
#include <cuda_runtime.h>
#include <math.h>

#define Bz 256
#define Sz 256
#define Mz 50
#define MP 25          // slot pairs
#define WST 52         // g_w row stride (padded, 16B-aligned float4 rows)
#define DQz 64
#define DVz 128
#define Fz 128
#define NQ1 10001
#define NQA1 20001
#define NROWS (Bz*Sz)

typedef unsigned long long u64;

// ---- packed f32x2 helpers (sm_103a FFMA2 path, PTX-only) -------------------
__device__ __forceinline__ u64 pack2(float lo, float hi) {
    u64 r; asm("mov.b64 %0, {%1, %2};" : "=l"(r) : "f"(lo), "f"(hi)); return r;
}
__device__ __forceinline__ void unpack2(u64 v, float& lo, float& hi) {
    asm("mov.b64 {%0, %1}, %2;" : "=f"(lo), "=f"(hi) : "l"(v));
}
__device__ __forceinline__ u64 fma2(u64 a, u64 b, u64 c) {
    u64 d; asm("fma.rn.f32x2 %0, %1, %2, %3;" : "=l"(d) : "l"(a), "l"(b), "l"(c)); return d;
}
__device__ __forceinline__ u64 add2(u64 a, u64 b) {
    u64 d; asm("add.rn.f32x2 %0, %1, %2;" : "=l"(d) : "l"(a), "l"(b)); return d;
}

// Scratch (static device globals — no allocation allowed)
__device__ float  g_w[NQ1 * WST];
__device__ float2 g_ea[NQA1 * DVz];   // interleaved (erase, add)
__device__ float  g_qr[NQ1 * Fz];
__device__ float  g_reads[NROWS * DVz];
__device__ float  g_acc[2];

// ---------------------------------------------------------------------------
__global__ void k_init() {
    if (threadIdx.x < 2) g_acc[threadIdx.x] = 0.0f;
}

// ---------------------------------------------------------------------------
__global__ void k_w(const float* __restrict__ q_table,
                    const float* __restrict__ key_mem) {
    __shared__ float key_s[Mz * DQz];
    int tid = threadIdx.x;
    for (int i = tid; i < Mz * DQz; i += blockDim.x) key_s[i] = key_mem[i];
    __syncthreads();

    int row = blockIdx.x * 128 + tid;
    if (row >= NQ1) return;

    float q[DQz];
    const float4* qp = (const float4*)(q_table + row * DQz);
#pragma unroll
    for (int i = 0; i < DQz / 4; i++) {
        float4 v = qp[i];
        q[4*i+0] = v.x; q[4*i+1] = v.y; q[4*i+2] = v.z; q[4*i+3] = v.w;
    }

    float sc[Mz];
    float mx = -1e30f;
#pragma unroll
    for (int m = 0; m < Mz; m++) {
        float s = 0.0f;
#pragma unroll
        for (int k = 0; k < DQz; k++) s = fmaf(q[k], key_s[m * DQz + k], s);
        sc[m] = s;
        mx = fmaxf(mx, s);
    }
    float sum = 0.0f;
#pragma unroll
    for (int m = 0; m < Mz; m++) {
        float e = __expf(sc[m] - mx);
        sc[m] = e;
        sum += e;
    }
    float inv = 1.0f / sum;
#pragma unroll
    for (int m = 0; m < Mz; m++) g_w[row * WST + m] = sc[m] * inv;
    g_w[row * WST + 50] = 0.0f;
    g_w[row * WST + 51] = 0.0f;
}

// ---------------------------------------------------------------------------
// q-part of the head: g_qr[i,:] = q_table[i,:] @ W_read[128:192,:]
#define QR_ROWS 64
#define QR_SMEM_FLOATS (64*128 + QR_ROWS*DQz)
__global__ void __launch_bounds__(512) k_qr(const float* __restrict__ q_table,
                                            const float* __restrict__ W_read) {
    extern __shared__ float sm[];
    float* W2 = sm;
    float* xs = W2 + 64 * 128;

    int tid = threadIdx.x;
    for (int i = tid; i < 64 * 128 / 4; i += 512)
        ((float4*)W2)[i] = ((const float4*)(W_read + 128 * 128))[i];

    int row0 = blockIdx.x * QR_ROWS;
    for (int idx = tid; idx < QR_ROWS * 16; idx += 512) {
        int r = idx >> 4, c = idx & 15;
        int row = row0 + r;
        float4 v = make_float4(0.f, 0.f, 0.f, 0.f);
        if (row < NQ1) v = ((const float4*)(q_table + (long)row * DQz))[c];
        ((float4*)xs)[r * 16 + c] = v;
    }
    __syncthreads();

    int rg = tid >> 4;
    int fg = tid & 15;
    u64 acc[2][4];
#pragma unroll
    for (int r = 0; r < 2; r++)
#pragma unroll
        for (int j = 0; j < 4; j++) acc[r][j] = 0ull;

#pragma unroll 4
    for (int k = 0; k < 64; k++) {
        const ulonglong2* wv = (const ulonglong2*)(W2 + k * 128 + fg * 8);
        ulonglong2 w01 = wv[0], w23 = wv[1];
#pragma unroll
        for (int r = 0; r < 2; r++) {
            float xv = xs[(rg * 2 + r) * DQz + k];
            u64 xp = pack2(xv, xv);
            acc[r][0] = fma2(xp, w01.x, acc[r][0]);
            acc[r][1] = fma2(xp, w01.y, acc[r][1]);
            acc[r][2] = fma2(xp, w23.x, acc[r][2]);
            acc[r][3] = fma2(xp, w23.y, acc[r][3]);
        }
    }

#pragma unroll
    for (int r = 0; r < 2; r++) {
        int row = row0 + rg * 2 + r;
        if (row < NQ1) {
            float v[8];
#pragma unroll
            for (int j = 0; j < 4; j++) unpack2(acc[r][j], v[2*j], v[2*j+1]);
            float4* op = (float4*)(g_qr + (long)row * Fz + fg * 8);
            op[0] = make_float4(v[0], v[1], v[2], v[3]);
            op[1] = make_float4(v[4], v[5], v[6], v[7]);
        }
    }
}

// ---------------------------------------------------------------------------
// Fused erase+add: one block computes BOTH tables for 136 rows.
// 544 threads (17 warps), grid = 148 = exactly one wave.
#define EA_ROWS 136
#define EA_THREADS 544
#define EA_GRID 148
#define EA_SMEM_FLOATS (2*16384 + EA_ROWS*DVz + 256)
__global__ void __launch_bounds__(EA_THREADS) k_ea(const float* __restrict__ qa_table,
                     const float* __restrict__ W_e, const float* __restrict__ b_e,
                     const float* __restrict__ W_a, const float* __restrict__ b_a) {
    extern __shared__ float sm[];
    float* We = sm;                  // 128x128
    float* Wa = We + 16384;          // 128x128
    float* xs = Wa + 16384;          // 136x128
    float* be = xs + EA_ROWS * DVz;  // 128
    float* ba = be + 128;            // 128

    int tid = threadIdx.x;
    for (int i = tid; i < 4096; i += EA_THREADS) {
        ((float4*)We)[i] = ((const float4*)W_e)[i];
        ((float4*)Wa)[i] = ((const float4*)W_a)[i];
    }
    if (tid < 128) { be[tid] = b_e[tid]; ba[tid] = b_a[tid]; }

    int row0 = blockIdx.x * EA_ROWS;
    for (int idx = tid; idx < EA_ROWS * 32; idx += EA_THREADS) {
        int r = idx >> 5, c = idx & 31;
        int row = row0 + r;
        float4 v = make_float4(0.f, 0.f, 0.f, 0.f);
        if (row < NQA1) v = ((const float4*)(qa_table + (long)row * DVz))[c];
        ((float4*)xs)[r * 32 + c] = v;
    }
    __syncthreads();

    int rg = tid >> 4;   // 34 groups of 4 rows
    int fg = tid & 15;   // 8 output cols (4 packed pairs)
    u64 ae[4][4], aa[4][4];
#pragma unroll
    for (int r = 0; r < 4; r++)
#pragma unroll
        for (int j = 0; j < 4; j++) { ae[r][j] = 0ull; aa[r][j] = 0ull; }

#pragma unroll 2
    for (int k = 0; k < DVz; k++) {
        const ulonglong2* wep = (const ulonglong2*)(We + k * DVz + fg * 8);
        const ulonglong2* wap = (const ulonglong2*)(Wa + k * DVz + fg * 8);
        ulonglong2 e01 = wep[0], e23 = wep[1];
        ulonglong2 a01 = wap[0], a23 = wap[1];
#pragma unroll
        for (int r = 0; r < 4; r++) {
            float xv = xs[(rg * 4 + r) * DVz + k];
            u64 xp = pack2(xv, xv);
            ae[r][0] = fma2(xp, e01.x, ae[r][0]);
            ae[r][1] = fma2(xp, e01.y, ae[r][1]);
            ae[r][2] = fma2(xp, e23.x, ae[r][2]);
            ae[r][3] = fma2(xp, e23.y, ae[r][3]);
            aa[r][0] = fma2(xp, a01.x, aa[r][0]);
            aa[r][1] = fma2(xp, a01.y, aa[r][1]);
            aa[r][2] = fma2(xp, a23.x, aa[r][2]);
            aa[r][3] = fma2(xp, a23.y, aa[r][3]);
        }
    }

#pragma unroll
    for (int r = 0; r < 4; r++) {
        int row = row0 + rg * 4 + r;
        if (row < NQA1) {
            float4 o[4];   // interleaved (er, ad) pairs
#pragma unroll
            for (int j = 0; j < 4; j++) {
                int f = fg * 8 + 2 * j;
                float s0, s1, t0, t1;
                unpack2(ae[r][j], s0, s1);
                unpack2(aa[r][j], t0, t1);
                o[j].x = 1.0f / (1.0f + __expf(-(s0 + be[f])));
                o[j].y = tanhf(t0 + ba[f]);
                o[j].z = 1.0f / (1.0f + __expf(-(s1 + be[f+1])));
                o[j].w = tanhf(t1 + ba[f+1]);
            }
            float4* op = (float4*)(g_ea + (long)row * DVz + fg * 8);
            op[0] = o[0]; op[1] = o[1]; op[2] = o[2]; op[3] = o[3];
        }
    }
}

// ---------------------------------------------------------------------------
// Scan: 128 blocks x 256 threads (2 batches/block), warp-private w staging,
// no block barrier in hot loop, 2-deep prefetch, single LDG.64 for (e,a).
__global__ void __launch_bounds__(256) k_scan(const int* __restrict__ q_data,
                                              const int* __restrict__ qa_data,
                                              const float* __restrict__ init_value) {
    __shared__ __align__(16) float w_s[8][3][56];   // per-warp triple-buffered
    __shared__ int qi_s[2][Sz], qa_s[2][Sz];

    int tid  = threadIdx.x;
    int half = tid >> 7;
    int d    = tid & 127;
    int warp = tid >> 5;
    int lane = tid & 31;

    int b = blockIdx.x * 2 + half;
    int base = b * Sz;

    for (int i = d; i < Sz; i += 128) {
        qi_s[half][i] = q_data[base + i];
        qa_s[half][i] = qa_data[base + i];
    }

    u64 mem[MP];
#pragma unroll
    for (int p = 0; p < MP; p++)
        mem[p] = pack2(init_value[(2*p) * DVz + d], init_value[(2*p+1) * DVz + d]);
    __syncthreads();

    // prime steps 0 and 1
    if (lane < 13) {
        ((float4*)w_s[warp][0])[lane] =
            ((const float4*)(g_w + qi_s[half][0] * WST))[lane];
        ((float4*)w_s[warp][1])[lane] =
            ((const float4*)(g_w + qi_s[half][1] * WST))[lane];
    }
    float2 ea0 = g_ea[qa_s[half][0] * DVz + d];
    float2 ea1 = g_ea[qa_s[half][1] * DVz + d];
    __syncwarp();

    int buf = 0;
    for (int s = 0; s < Sz; s++) {
        bool flag = (qi_s[half][s] >= 1);

        // prefetch step s+2
        float2 ea2 = make_float2(0.f, 0.f);
        if (s + 2 < Sz) {
            ea2 = g_ea[qa_s[half][s + 2] * DVz + d];
            if (lane < 13) {
                int nb = buf + 2; if (nb >= 3) nb -= 3;
                ((float4*)w_s[warp][nb])[lane] =
                    ((const float4*)(g_w + qi_s[half][s + 2] * WST))[lane];
            }
        }

        u64 ne = pack2(ea0.x, ea0.x) ^ 0x8000000080000000ull;   // (-e, -e)
        u64 av = pack2(ea0.y, ea0.y);

        // read: 12 LDS.128 + 1 LDS.64
        const ulonglong2* wv = (const ulonglong2*)w_s[warp][buf];
        u64 wr[MP];
        u64 r0 = 0ull, r1 = 0ull, r2 = 0ull, r3 = 0ull;
#pragma unroll
        for (int i = 0; i < 12; i += 2) {
            ulonglong2 t0 = wv[i], t1 = wv[i + 1];
            wr[2*i+0] = t0.x; r0 = fma2(t0.x, mem[2*i+0], r0);
            wr[2*i+1] = t0.y; r1 = fma2(t0.y, mem[2*i+1], r1);
            wr[2*i+2] = t1.x; r2 = fma2(t1.x, mem[2*i+2], r2);
            wr[2*i+3] = t1.y; r3 = fma2(t1.y, mem[2*i+3], r3);
        }
        wr[24] = ((const u64*)w_s[warp][buf])[24];
        r0 = fma2(wr[24], mem[24], r0);
        u64 rr = add2(add2(r0, r1), add2(r2, r3));
        float lo, hi;
        unpack2(rr, lo, hi);
        g_reads[(long)(base + s) * DVz + d] = lo + hi;

        // update (uniform branch per warp)
        if (flag) {
#pragma unroll
            for (int p = 0; p < MP; p++) {
                u64 t = fma2(ne, mem[p], av);
                mem[p] = fma2(wr[p], t, mem[p]);
            }
        }

        ea0 = ea1; ea1 = ea2;
        __syncwarp();
        buf += 1; if (buf == 3) buf = 0;
    }
}

// ---------------------------------------------------------------------------
// Head: K=128 GEMM on reads; 512 threads, 256 rows/block, 8x8 register tile.
#define HD_ROWS 256
#define HEAD_SMEM_FLOATS (128*128 + HD_ROWS*128 + 128 + 128 + HD_ROWS + 2)
__global__ void __launch_bounds__(512) k_head(const int* __restrict__ q_data,
                       const float* __restrict__ target,
                       const float* __restrict__ W_read, const float* __restrict__ b_read,
                       const float* __restrict__ W_pred, const float* __restrict__ b_pred,
                       float* __restrict__ out) {
    extern __shared__ float sm[];
    float* Ws = sm;                   // 128 x 128
    float* xs = Ws + 128 * 128;       // 256 rows x 128
    float* br = xs + HD_ROWS * 128;
    float* wp = br + 128;
    float* lo = wp + 128;
    float* ls = lo + HD_ROWS;

    int tid = threadIdx.x;
    for (int i = tid; i < 128 * 128 / 4; i += 512)
        ((float4*)Ws)[i] = ((const float4*)W_read)[i];
    if (tid < 128) { br[tid] = b_read[tid]; wp[tid] = W_pred[tid]; }
    if (tid < 2)   ls[tid] = 0.0f;

    int row0 = blockIdx.x * HD_ROWS;
    for (int idx = tid; idx < HD_ROWS * 32; idx += 512) {
        int r = idx >> 5, c = idx & 31;
        int row = row0 + r;
        ((float4*)(xs + r * 128))[c] = ((const float4*)(g_reads + (long)row * DVz))[c];
    }
    __syncthreads();

    int rg = tid >> 4;  // 32 groups x 8 rows
    int fg = tid & 15;  // 8 f-cols (4 packed pairs)
    u64 acc[8][4];
#pragma unroll
    for (int r = 0; r < 8; r++)
#pragma unroll
        for (int j = 0; j < 4; j++) acc[r][j] = 0ull;

#pragma unroll 2
    for (int k = 0; k < 128; k++) {
        const ulonglong2* wv = (const ulonglong2*)(Ws + k * 128 + fg * 8);
        ulonglong2 w01 = wv[0], w23 = wv[1];
#pragma unroll
        for (int r = 0; r < 8; r++) {
            float xv = xs[(rg * 8 + r) * 128 + k];
            u64 xp = pack2(xv, xv);
            acc[r][0] = fma2(xp, w01.x, acc[r][0]);
            acc[r][1] = fma2(xp, w01.y, acc[r][1]);
            acc[r][2] = fma2(xp, w23.x, acc[r][2]);
            acc[r][3] = fma2(xp, w23.y, acc[r][3]);
        }
    }

    float bp = __ldg(b_pred);
#pragma unroll
    for (int r = 0; r < 8; r++) {
        int row = row0 + rg * 8 + r;
        int qi = q_data[row];
        const float4* qrp = (const float4*)(g_qr + (long)qi * Fz + fg * 8);
        float4 q0 = qrp[0], q1 = qrp[1];
        float qv[8] = {q0.x, q0.y, q0.z, q0.w, q1.x, q1.y, q1.z, q1.w};
        float p = 0.0f;
#pragma unroll
        for (int j = 0; j < 4; j++) {
            int f = fg * 8 + 2 * j;
            float s0, s1;
            unpack2(acc[r][j], s0, s1);
            p = fmaf(tanhf(s0 + qv[2*j]   + br[f]),     wp[f],     p);
            p = fmaf(tanhf(s1 + qv[2*j+1] + br[f + 1]), wp[f + 1], p);
        }
#pragma unroll
        for (int off = 8; off >= 1; off >>= 1)
            p += __shfl_down_sync(0xffffffffu, p, off, 16);
        if (fg == 0) lo[rg * 8 + r] = p + bp;
    }
    __syncthreads();

    for (int t = tid; t < HD_ROWS; t += 512) {
        int row = row0 + t;
        float l = lo[t];
        float prob = 1.0f / (1.0f + __expf(-l));
        out[1 + row] = prob;
        float tt = target[row];
        float bce = 0.0f, cnt = 0.0f;
        if (tt >= 0.0f) {
            bce = fmaxf(l, 0.0f) - l * tt + log1pf(__expf(-fabsf(l)));
            cnt = 1.0f;
        }
#pragma unroll
        for (int off = 16; off >= 1; off >>= 1) {
            bce += __shfl_down_sync(0xffffffffu, bce, off);
            cnt += __shfl_down_sync(0xffffffffu, cnt, off);
        }
        if ((tid & 31) == 0) {
            atomicAdd(&ls[0], bce);
            atomicAdd(&ls[1], cnt);
        }
    }
    __syncthreads();
    if (tid == 0) {
        atomicAdd(&g_acc[0], ls[0]);
        atomicAdd(&g_acc[1], ls[1]);
    }
}

// ---------------------------------------------------------------------------
__global__ void k_fin(float* __restrict__ out) {
    out[0] = g_acc[0] / fmaxf(g_acc[1], 1.0f);
}

// ---------------------------------------------------------------------------
extern "C" void kernel_launch(void* const* d_in, const int* in_sizes, int n_in,
                              void* d_out, int out_size) {
    const int*   q_data    = (const int*)d_in[0];
    const int*   qa_data   = (const int*)d_in[1];
    const float* target    = (const float*)d_in[2];
    const float* q_table   = (const float*)d_in[3];
    const float* qa_table  = (const float*)d_in[4];
    const float* key_mem   = (const float*)d_in[5];
    const float* init_value= (const float*)d_in[6];
    const float* W_e    = (const float*)d_in[7];
    const float* b_e    = (const float*)d_in[8];
    const float* W_a    = (const float*)d_in[9];
    const float* b_a    = (const float*)d_in[10];
    const float* W_read = (const float*)d_in[11];
    const float* b_read = (const float*)d_in[12];
    const float* W_pred = (const float*)d_in[13];
    const float* b_pred = (const float*)d_in[14];
    float* out = (float*)d_out;

    cudaFuncSetAttribute(k_ea, cudaFuncAttributeMaxDynamicSharedMemorySize,
                         EA_SMEM_FLOATS * (int)sizeof(float));
    cudaFuncSetAttribute(k_head, cudaFuncAttributeMaxDynamicSharedMemorySize,
                         HEAD_SMEM_FLOATS * (int)sizeof(float));
    cudaFuncSetAttribute(k_qr, cudaFuncAttributeMaxDynamicSharedMemorySize,
                         QR_SMEM_FLOATS * (int)sizeof(float));

    k_init<<<1, 32>>>();
    k_w<<<(NQ1 + 127) / 128, 128>>>(q_table, key_mem);
    k_qr<<<(NQ1 + QR_ROWS - 1) / QR_ROWS, 512, QR_SMEM_FLOATS * sizeof(float)>>>(
        q_table, W_read);
    k_ea<<<EA_GRID, EA_THREADS, EA_SMEM_FLOATS * sizeof(float)>>>(
        qa_table, W_e, b_e, W_a, b_a);
    k_scan<<<Bz / 2, 256>>>(q_data, qa_data, init_value);
    k_head<<<NROWS / HD_ROWS, 512, HEAD_SMEM_FLOATS * sizeof(float)>>>(
        q_data, target, W_read, b_read, W_pred, b_pred, out);
    k_fin<<<1, 1>>>(out);
}